// round 9
// baseline (speedup 1.0000x reference)
#include <cuda_runtime.h>

// LSTM_74122545594502: 3-layer bidirectional LSTM, B=4096 T=256 D=4 H=16.
// Round 9: round-8 design (NB=8 chains/warp, skewed layers, f32x2 chain
// packing) with the iteration RESTRUCTURED as
//   L3-gates -> U3 -> L2-gates -> U2 -> L1-gates -> U1
// so each update's MUFU/SHFL dependency chain hides under the next gate
// block's FFMA2 stream, and accumulator liveness drops from 24 ull to 8 ull.

namespace {
constexpr int B_ = 4096;
constexpr int T_ = 256;
constexpr int D_ = 4;
constexpr int H_ = 16;
constexpr int NB = 8;                      // chains per warp
constexpr int WPC = 4;                     // warps per CTA
constexpr int NCTA = 2 * (B_ / NB) / WPC;  // 256
constexpr int WPITCH = 36;                 // smem weight row pitch (floats)
}

typedef unsigned long long ull;

__device__ __forceinline__ ull pack2(float x, float y) {
    ull r;
    asm("mov.b64 %0, {%1, %2};" : "=l"(r) : "f"(x), "f"(y));
    return r;
}
__device__ __forceinline__ void unpack2(ull v, float& x, float& y) {
    asm("mov.b64 {%0, %1}, %2;" : "=f"(x), "=f"(y) : "l"(v));
}
__device__ __forceinline__ ull ffma2(ull a, ull b, ull c) {
    ull d;
    asm("fma.rn.f32x2 %0, %1, %2, %3;" : "=l"(d) : "l"(a), "l"(b), "l"(c));
    return d;
}
__device__ __forceinline__ ull mul2(ull a, ull b) {
    ull d;
    asm("mul.rn.f32x2 %0, %1, %2;" : "=l"(d) : "l"(a), "l"(b));
    return d;
}

// sigmoid(v) = 1/(1+exp(-v)); tanh(v) = 2*sigmoid(2v)-1.
__device__ __forceinline__ float fast_act(float v, bool is_tanh) {
    float arg = is_tanh ? (-2.0f * v) : (-v);
    float e = __expf(arg);
    float r = __fdividef(1.0f, 1.0f + e);
    return is_tanh ? (2.0f * r - 1.0f) : r;
}
__device__ __forceinline__ float fast_tanh(float v) { return fast_act(v, true); }

struct Params {
    const float* y;
    const float* w[24];  // dir*12 + {Wih1,Whh1,bih1,bhh1, Wih2,...,bhh3}
};

__device__ float g_h3[2][B_][H_];  // final layer-3 h

// One input index j: 2 broadcast LDS.128 feed 8 FFMA2 (8 chains, 2 rows).
__device__ __forceinline__ void gstep8(ull wp0, ull wp1, const float* vj,
                                       ull* A, ull* B) {
    ulonglong2 v01 = *(const ulonglong2*)(vj);
    ulonglong2 v23 = *(const ulonglong2*)(vj + 4);
    A[0] = ffma2(wp0, v01.x, A[0]);
    A[1] = ffma2(wp0, v01.y, A[1]);
    A[2] = ffma2(wp0, v23.x, A[2]);
    A[3] = ffma2(wp0, v23.y, A[3]);
    B[0] = ffma2(wp1, v01.x, B[0]);
    B[1] = ffma2(wp1, v01.y, B[1]);
    B[2] = ffma2(wp1, v23.x, B[2]);
    B[3] = ffma2(wp1, v23.y, B[3]);
}

// Layer-1 gates: register weights. A rows carry r0 (bias bplo), B rows r1.
__device__ __forceinline__ void gates_l1(
    const float* xin, const float* hin,
    const float* wi0, const float* wi1, const float* wh0, const float* wh1,
    ull bplo, ull bphi, ull* A, ull* B)
{
#pragma unroll
    for (int k = 0; k < 4; ++k) { A[k] = bplo; B[k] = bphi; }
#pragma unroll
    for (int j = 0; j < D_; ++j)
        gstep8(pack2(wi0[j], wi0[j]), pack2(wi1[j], wi1[j]), xin + 8 * j, A, B);
#pragma unroll
    for (int j = 0; j < H_; ++j)
        gstep8(pack2(wh0[j], wh0[j]), pack2(wh1[j], wh1[j]), hin + 8 * j, A, B);
}

// Layer-2/3 gates: scalar weights from smem (float4 loads + MOV dup).
__device__ __forceinline__ void gates_l23(
    const float (*wsmL)[WPITCH], int r0, int r1,
    const float* inA, const float* inB,
    ull bplo, ull bphi, ull* A, ull* B)
{
#pragma unroll
    for (int k = 0; k < 4; ++k) { A[k] = bplo; B[k] = bphi; }
#pragma unroll
    for (int jq = 0; jq < 4; ++jq) {
        float4 w0 = *(const float4*)&wsmL[r0][4 * jq];
        float4 w1 = *(const float4*)&wsmL[r1][4 * jq];
        gstep8(pack2(w0.x, w0.x), pack2(w1.x, w1.x), inA + 8 * (4 * jq + 0), A, B);
        gstep8(pack2(w0.y, w0.y), pack2(w1.y, w1.y), inA + 8 * (4 * jq + 1), A, B);
        gstep8(pack2(w0.z, w0.z), pack2(w1.z, w1.z), inA + 8 * (4 * jq + 2), A, B);
        gstep8(pack2(w0.w, w0.w), pack2(w1.w, w1.w), inA + 8 * (4 * jq + 3), A, B);
    }
#pragma unroll
    for (int jq = 4; jq < 8; ++jq) {
        float4 w0 = *(const float4*)&wsmL[r0][4 * jq];
        float4 w1 = *(const float4*)&wsmL[r1][4 * jq];
        gstep8(pack2(w0.x, w0.x), pack2(w1.x, w1.x), inB + 8 * (4 * jq - 16), A, B);
        gstep8(pack2(w0.y, w0.y), pack2(w1.y, w1.y), inB + 8 * (4 * jq - 15), A, B);
        gstep8(pack2(w0.z, w0.z), pack2(w1.z, w1.z), inB + 8 * (4 * jq - 14), A, B);
        gstep8(pack2(w0.w, w0.w), pack2(w1.w, w1.w), inB + 8 * (4 * jq - 13), A, B);
    }
}

// Activate + bfly(16) exchange + c/h update for 8 chains.
// Low lane ends with chains 0-3 of its unit; high lane chains 4-7.
__device__ __forceinline__ float4 do_update8(ull* A, ull* B, bool low,
                                             ull& c0, ull& c1, float* hdst) {
    float af[8], bf[8];
#pragma unroll
    for (int k = 0; k < 4; ++k) {
        unpack2(A[k], af[2 * k], af[2 * k + 1]);
        unpack2(B[k], bf[2 * k], bf[2 * k + 1]);
    }
#pragma unroll
    for (int i = 0; i < 8; ++i) {
        af[i] = fast_act(af[i], false);   // i (low) / f (high): sigmoid
        bf[i] = fast_act(bf[i], low);     // g (low): tanh; o (high): sigmoid
    }
#pragma unroll
    for (int k = 0; k < 4; ++k) {
        A[k] = pack2(af[2 * k], af[2 * k + 1]);
        B[k] = pack2(bf[2 * k], bf[2 * k + 1]);
    }
    ull s0 = low ? A[2] : A[0];
    ull s1 = low ? A[3] : A[1];
    ull s2 = low ? B[2] : B[0];
    ull s3 = low ? B[3] : B[1];
    ull r0 = __shfl_xor_sync(0xffffffffu, s0, 16);
    ull r1 = __shfl_xor_sync(0xffffffffu, s1, 16);
    ull r2 = __shfl_xor_sync(0xffffffffu, s2, 16);
    ull r3 = __shfl_xor_sync(0xffffffffu, s3, 16);
    ull I0 = low ? A[0] : r0, I1 = low ? A[1] : r1;
    ull F0 = low ? r0 : A[2], F1 = low ? r1 : A[3];
    ull G0 = low ? B[0] : r2, G1 = low ? B[1] : r3;
    ull O0 = low ? r2 : B[2], O1 = low ? r3 : B[3];
    c0 = ffma2(F0, c0, mul2(I0, G0));
    c1 = ffma2(F1, c1, mul2(I1, G1));
    float ca0, ca1, ca2, ca3, o0, o1, o2, o3;
    unpack2(c0, ca0, ca1);
    unpack2(c1, ca2, ca3);
    unpack2(O0, o0, o1);
    unpack2(O1, o2, o3);
    float4 h = make_float4(o0 * fast_tanh(ca0), o1 * fast_tanh(ca1),
                           o2 * fast_tanh(ca2), o3 * fast_tanh(ca3));
    *(float4*)hdst = h;
    return h;
}

__global__ void __launch_bounds__(128, 2) lstm_kernel(Params p) {
    __shared__ float wsm[2][64][WPITCH];    // L2/L3 weights [layer][row][ih|hh]
    __shared__ __align__(16) float xs[WPC][2][D_][NB];     // x per warp
    __shared__ __align__(16) float hs[WPC][3][2][H_][NB];  // h per warp/layer

    const int tid  = threadIdx.x;
    const int lane = tid & 31;
    const int w    = tid >> 5;
    const int dir  = blockIdx.x >> 7;                // 128 CTAs per dir
    const int gidx = (blockIdx.x & 127) * WPC + w;   // 0..511 per dir
    const int b0   = gidx * NB;
    const bool low = lane < 16;
    const int unit = lane & 15;

    const float* const* ws = &p.w[dir * 12];

    // ---- cooperative fill of L2/L3 weight table ----
    for (int i = tid; i < 2 * 64 * 32; i += 128) {
        int layer = i >> 11, rem = i & 2047, row = rem >> 5, col = rem & 31;
        float v = (col < 16) ? ws[4 + layer * 4][row * 16 + col]
                             : ws[5 + layer * 4][row * 16 + (col - 16)];
        wsm[layer][row][col] = v;
    }

    // ---- L1 weights + per-row duplicated biases in registers ----
    const int r0 = lane, r1 = lane + 32;
    float wi0[D_], wi1[D_], wh0[H_], wh1[H_];
#pragma unroll
    for (int j = 0; j < D_; ++j) { wi0[j] = ws[0][r0 * D_ + j]; wi1[j] = ws[0][r1 * D_ + j]; }
#pragma unroll
    for (int j = 0; j < H_; ++j) { wh0[j] = ws[1][r0 * H_ + j]; wh1[j] = ws[1][r1 * H_ + j]; }
    const float b1l = ws[2][r0] + ws[3][r0],   b1h = ws[2][r1] + ws[3][r1];
    const float b2l = ws[6][r0] + ws[7][r0],   b2h = ws[6][r1] + ws[7][r1];
    const float b3l = ws[10][r0] + ws[11][r0], b3h = ws[10][r1] + ws[11][r1];
    const ull bp1l = pack2(b1l, b1l), bp1h = pack2(b1h, b1h);
    const ull bp2l = pack2(b2l, b2l), bp2h = pack2(b2h, b2h);
    const ull bp3l = pack2(b3l, b3l), bp3h = pack2(b3h, b3h);

    // ---- init: both h buffers zero; x buffer 0 = x[step 0] ----
    {
        float4* hp = (float4*)&hs[w][0][0][0][0];
#pragma unroll
        for (int i = lane; i < 3 * 2 * H_ * NB / 4; i += 32)
            hp[i] = make_float4(0.f, 0.f, 0.f, 0.f);
    }
    const int xc = lane >> 2, xj = lane & 3;  // chain 0..7, component 0..3
    {
        int tt = dir ? (T_ - 1) : 0;
        xs[w][0][xj][xc] = p.y[((size_t)(b0 + xc) * T_ + tt) * D_ + xj];
    }
    __syncthreads();  // weight table + buffers visible

    ull c1p0 = 0ull, c1p1 = 0ull, c2p0 = 0ull, c2p1 = 0ull, c3p0 = 0ull, c3p1 = 0ull;
    float4 h3f = make_float4(0.f, 0.f, 0.f, 0.f);
    const int hoff = low ? 0 : 4;

    // Iteration K (skewed): L3(step K-2) gates+update, then L2(step K-1),
    // then L1(step K) — each update's MUFU/SHFL chain hides under the next
    // gate block's FFMA2 stream. All gates read buffer rb=K&1 (old values);
    // all updates write wb=rb^1. U1/U2/U3 enable the updates.
#define ITER(K, U1, U2, U3) do {                                              \
    const int rb_ = (K) & 1, wb_ = rb_ ^ 1;                                   \
    int tt_ = dir ? (T_ - 2 - (K)) : ((K) + 1);                               \
    tt_ = tt_ < 0 ? 0 : (tt_ > T_ - 1 ? T_ - 1 : tt_);                        \
    float xn_ = p.y[((size_t)(b0 + xc) * T_ + tt_) * D_ + xj];                \
    ull A_[4], B_[4];                                                         \
    gates_l23(wsm[1], r0, r1,                                                 \
              &hs[w][1][rb_][0][0], &hs[w][2][rb_][0][0],                     \
              bp3l, bp3h, A_, B_);                                            \
    if (U3) h3f = do_update8(A_, B_, low, c3p0, c3p1,                         \
                             &hs[w][2][wb_][unit][0] + hoff);                 \
    gates_l23(wsm[0], r0, r1,                                                 \
              &hs[w][0][rb_][0][0], &hs[w][1][rb_][0][0],                     \
              bp2l, bp2h, A_, B_);                                            \
    if (U2) do_update8(A_, B_, low, c2p0, c2p1,                               \
                       &hs[w][1][wb_][unit][0] + hoff);                       \
    gates_l1(&xs[w][rb_][0][0], &hs[w][0][rb_][0][0],                         \
             wi0, wi1, wh0, wh1, bp1l, bp1h, A_, B_);                         \
    if (U1) do_update8(A_, B_, low, c1p0, c1p1,                               \
                       &hs[w][0][wb_][unit][0] + hoff);                       \
    xs[w][wb_][xj][xc] = xn_;                                                 \
    __syncwarp();                                                             \
} while (0)

    ITER(0, true, false, false);
    ITER(1, true, true, false);
#pragma unroll 1
    for (int k = 2; k < T_; ++k) ITER(k, true, true, true);
    ITER(T_, false, true, true);
    ITER(T_ + 1, false, false, true);
#undef ITER

    // final layer-3 h (step T-1): low lane -> chains 0-3; high -> 4-7.
    {
        int cb = b0 + (low ? 0 : 4);
        g_h3[dir][cb + 0][unit] = h3f.x;
        g_h3[dir][cb + 1][unit] = h3f.y;
        g_h3[dir][cb + 2][unit] = h3f.z;
        g_h3[dir][cb + 3][unit] = h3f.w;
    }
}

// out[b,k] = b_out[k] + sum_j W_out[k][j]*hf3[b][j] + W_out[k][16+j]*hb3[b][j]
__global__ void proj_kernel(const float* __restrict__ Wo,
                            const float* __restrict__ bo,
                            float* __restrict__ out) {
    int b = blockIdx.x * blockDim.x + threadIdx.x;
    if (b >= B_) return;
    float a0 = bo[0], a1 = bo[1], a2 = bo[2], a3 = bo[3];
#pragma unroll
    for (int j = 0; j < H_; ++j) {
        float hf = g_h3[0][b][j];
        a0 += Wo[0 * 32 + j] * hf;
        a1 += Wo[1 * 32 + j] * hf;
        a2 += Wo[2 * 32 + j] * hf;
        a3 += Wo[3 * 32 + j] * hf;
    }
#pragma unroll
    for (int j = 0; j < H_; ++j) {
        float hb = g_h3[1][b][j];
        a0 += Wo[0 * 32 + 16 + j] * hb;
        a1 += Wo[1 * 32 + 16 + j] * hb;
        a2 += Wo[2 * 32 + 16 + j] * hb;
        a3 += Wo[3 * 32 + 16 + j] * hb;
    }
    ((float4*)out)[b] = make_float4(a0, a1, a2, a3);
}

extern "C" void kernel_launch(void* const* d_in, const int* in_sizes, int n_in,
                              void* d_out, int out_size) {
    (void)in_sizes; (void)n_in; (void)out_size;
    Params p;
    p.y = (const float*)d_in[0];
    for (int i = 0; i < 24; ++i) p.w[i] = (const float*)d_in[1 + i];

    lstm_kernel<<<NCTA, 128>>>(p);
    proj_kernel<<<(B_ + 127) / 128, 128>>>((const float*)d_in[25],
                                           (const float*)d_in[26],
                                           (float*)d_out);
}

// round 10
// speedup vs baseline: 1.1116x; 1.1116x over previous
#include <cuda_runtime.h>

// LSTM_74122545594502: 3-layer bidirectional LSTM, B=4096 T=256 D=4 H=16.
// Round 10: round-8 skeleton (NB=8 chains/warp, skewed layers L1(K)/L2(K-1)/
// L3(K-2), f32x2 chain packing, bfly(16) update) with:
//  - 256-thread CTAs (WPC=8), NCTA=128 -> uniform 1 CTA/SM, no stragglers
//  - fused gate blocks: h0 read once (L1-hh + L2-ih), h1 once (L2-hh + L3-ih)
//  - staggered updates: U1 after block A, U2 after B, U3 after C
//  - L1 weights pre-packed as duplicated f32x2 pairs (no in-loop MOV dup)

namespace {
constexpr int B_ = 4096;
constexpr int T_ = 256;
constexpr int D_ = 4;
constexpr int H_ = 16;
constexpr int NB = 8;                      // chains per warp
constexpr int WPC = 8;                     // warps per CTA
constexpr int NCTA = 2 * (B_ / NB) / WPC;  // 128
constexpr int WPITCH = 36;                 // smem weight row pitch (floats)
}

typedef unsigned long long ull;

__device__ __forceinline__ ull pack2(float x, float y) {
    ull r;
    asm("mov.b64 %0, {%1, %2};" : "=l"(r) : "f"(x), "f"(y));
    return r;
}
__device__ __forceinline__ void unpack2(ull v, float& x, float& y) {
    asm("mov.b64 {%0, %1}, %2;" : "=f"(x), "=f"(y) : "l"(v));
}
__device__ __forceinline__ ull ffma2(ull a, ull b, ull c) {
    ull d;
    asm("fma.rn.f32x2 %0, %1, %2, %3;" : "=l"(d) : "l"(a), "l"(b), "l"(c));
    return d;
}
__device__ __forceinline__ ull mul2(ull a, ull b) {
    ull d;
    asm("mul.rn.f32x2 %0, %1, %2;" : "=l"(d) : "l"(a), "l"(b));
    return d;
}

// sigmoid(v) = 1/(1+exp(-v)); tanh(v) = 2*sigmoid(2v)-1.
__device__ __forceinline__ float fast_act(float v, bool is_tanh) {
    float arg = is_tanh ? (-2.0f * v) : (-v);
    float e = __expf(arg);
    float r = __fdividef(1.0f, 1.0f + e);
    return is_tanh ? (2.0f * r - 1.0f) : r;
}
__device__ __forceinline__ float fast_tanh(float v) { return fast_act(v, true); }

struct Params {
    const float* y;
    const float* w[24];  // dir*12 + {Wih1,Whh1,bih1,bhh1, Wih2,...,bhh3}
};

__device__ float g_h3[2][B_][H_];  // final layer-3 h

// 8 FFMA2 for one input index j (8 chains, 2 gate rows); v already loaded.
__device__ __forceinline__ void gstep8v(ull wp0, ull wp1,
                                        ulonglong2 v01, ulonglong2 v23,
                                        ull* A, ull* B) {
    A[0] = ffma2(wp0, v01.x, A[0]);
    A[1] = ffma2(wp0, v01.y, A[1]);
    A[2] = ffma2(wp0, v23.x, A[2]);
    A[3] = ffma2(wp0, v23.y, A[3]);
    B[0] = ffma2(wp1, v01.x, B[0]);
    B[1] = ffma2(wp1, v01.y, B[1]);
    B[2] = ffma2(wp1, v23.x, B[2]);
    B[3] = ffma2(wp1, v23.y, B[3]);
}

// Activate + bfly(16) exchange + c/h update for 8 chains (round-8 validated).
__device__ __forceinline__ float4 do_update8(ull* A, ull* B, bool low,
                                             ull& c0, ull& c1, float* hdst) {
    float af[8], bf[8];
#pragma unroll
    for (int k = 0; k < 4; ++k) {
        unpack2(A[k], af[2 * k], af[2 * k + 1]);
        unpack2(B[k], bf[2 * k], bf[2 * k + 1]);
    }
#pragma unroll
    for (int i = 0; i < 8; ++i) {
        af[i] = fast_act(af[i], false);   // i (low) / f (high): sigmoid
        bf[i] = fast_act(bf[i], low);     // g (low): tanh; o (high): sigmoid
    }
#pragma unroll
    for (int k = 0; k < 4; ++k) {
        A[k] = pack2(af[2 * k], af[2 * k + 1]);
        B[k] = pack2(bf[2 * k], bf[2 * k + 1]);
    }
    ull s0 = low ? A[2] : A[0];
    ull s1 = low ? A[3] : A[1];
    ull s2 = low ? B[2] : B[0];
    ull s3 = low ? B[3] : B[1];
    ull r0 = __shfl_xor_sync(0xffffffffu, s0, 16);
    ull r1 = __shfl_xor_sync(0xffffffffu, s1, 16);
    ull r2 = __shfl_xor_sync(0xffffffffu, s2, 16);
    ull r3 = __shfl_xor_sync(0xffffffffu, s3, 16);
    ull I0 = low ? A[0] : r0, I1 = low ? A[1] : r1;
    ull F0 = low ? r0 : A[2], F1 = low ? r1 : A[3];
    ull G0 = low ? B[0] : r2, G1 = low ? B[1] : r3;
    ull O0 = low ? r2 : B[2], O1 = low ? r3 : B[3];
    c0 = ffma2(F0, c0, mul2(I0, G0));
    c1 = ffma2(F1, c1, mul2(I1, G1));
    float ca0, ca1, ca2, ca3, o0, o1, o2, o3;
    unpack2(c0, ca0, ca1);
    unpack2(c1, ca2, ca3);
    unpack2(O0, o0, o1);
    unpack2(O1, o2, o3);
    float4 h = make_float4(o0 * fast_tanh(ca0), o1 * fast_tanh(ca1),
                           o2 * fast_tanh(ca2), o3 * fast_tanh(ca3));
    *(float4*)hdst = h;
    return h;
}

__global__ void __launch_bounds__(256, 1) lstm_kernel(Params p) {
    __shared__ float wsm[2][64][WPITCH];    // L2/L3 weights [layer][row][ih|hh]
    __shared__ __align__(16) float xs[WPC][2][D_][NB];     // x per warp
    __shared__ __align__(16) float hs[WPC][3][2][H_][NB];  // h per warp/layer

    const int tid  = threadIdx.x;
    const int lane = tid & 31;
    const int w    = tid >> 5;
    const int dir  = blockIdx.x >> 6;               // 64 CTAs per dir
    const int gidx = (blockIdx.x & 63) * WPC + w;   // 0..511 per dir
    const int b0   = gidx * NB;
    const bool low = lane < 16;
    const int unit = lane & 15;

    const float* const* ws = &p.w[dir * 12];

    // ---- cooperative fill of L2/L3 weight table ----
    for (int i = tid; i < 2 * 64 * 32; i += 256) {
        int layer = i >> 11, rem = i & 2047, row = rem >> 5, col = rem & 31;
        float v = (col < 16) ? ws[4 + layer * 4][row * 16 + col]
                             : ws[5 + layer * 4][row * 16 + (col - 16)];
        wsm[layer][row][col] = v;
    }

    // ---- L1 weights pre-packed (duplicated) + per-row biases ----
    const int r0 = lane, r1 = lane + 32;
    ull wxp0[D_], wxp1[D_], whp0[H_], whp1[H_];
#pragma unroll
    for (int j = 0; j < D_; ++j) {
        float a = ws[0][r0 * D_ + j], b = ws[0][r1 * D_ + j];
        wxp0[j] = pack2(a, a);
        wxp1[j] = pack2(b, b);
    }
#pragma unroll
    for (int j = 0; j < H_; ++j) {
        float a = ws[1][r0 * H_ + j], b = ws[1][r1 * H_ + j];
        whp0[j] = pack2(a, a);
        whp1[j] = pack2(b, b);
    }
    const float b1l = ws[2][r0] + ws[3][r0],   b1h = ws[2][r1] + ws[3][r1];
    const float b2l = ws[6][r0] + ws[7][r0],   b2h = ws[6][r1] + ws[7][r1];
    const float b3l = ws[10][r0] + ws[11][r0], b3h = ws[10][r1] + ws[11][r1];
    const ull bp1l = pack2(b1l, b1l), bp1h = pack2(b1h, b1h);
    const ull bp2l = pack2(b2l, b2l), bp2h = pack2(b2h, b2h);
    const ull bp3l = pack2(b3l, b3l), bp3h = pack2(b3h, b3h);

    // ---- init: both h buffers zero; x buffer 0 = x[step 0] ----
    {
        float4* hp = (float4*)&hs[w][0][0][0][0];
#pragma unroll
        for (int i = lane; i < 3 * 2 * H_ * NB / 4; i += 32)
            hp[i] = make_float4(0.f, 0.f, 0.f, 0.f);
    }
    const int xc = lane >> 2, xj = lane & 3;  // chain 0..7, component 0..3
    {
        int tt = dir ? (T_ - 1) : 0;
        xs[w][0][xj][xc] = p.y[((size_t)(b0 + xc) * T_ + tt) * D_ + xj];
    }
    __syncthreads();  // weight table + buffers visible

    ull c1p0 = 0ull, c1p1 = 0ull, c2p0 = 0ull, c2p1 = 0ull, c3p0 = 0ull, c3p1 = 0ull;
    float4 h3f = make_float4(0.f, 0.f, 0.f, 0.f);
    const int hoff = low ? 0 : 4;

    // Iteration K (skewed): gates of L1(step K), L2(K-1), L3(K-2), all read
    // buffer rb=K&1, updates write wb. Fused input loads:
    //  block A: x->L1; h0->L1-hh & L2-ih;  U1
    //  block B: h1->L2-hh & L3-ih;         U2
    //  block C: h2->L3-hh;                 U3
#define ITER(K, U1, U2, U3) do {                                              \
    const int rb_ = (K) & 1, wb_ = rb_ ^ 1;                                   \
    int tt_ = dir ? (T_ - 2 - (K)) : ((K) + 1);                               \
    tt_ = tt_ < 0 ? 0 : (tt_ > T_ - 1 ? T_ - 1 : tt_);                        \
    float xn_ = p.y[((size_t)(b0 + xc) * T_ + tt_) * D_ + xj];                \
    ull A1_[4], B1_[4], A2_[4], B2_[4], A3_[4], B3_[4];                       \
    _Pragma("unroll")                                                         \
    for (int k_ = 0; k_ < 4; ++k_) {                                          \
        A1_[k_] = bp1l; B1_[k_] = bp1h;                                       \
        A2_[k_] = bp2l; B2_[k_] = bp2h;                                       \
    }                                                                         \
    /* block A */                                                             \
    {                                                                         \
        const ulonglong2* xv = (const ulonglong2*)&xs[w][rb_][0][0];          \
        _Pragma("unroll")                                                     \
        for (int j_ = 0; j_ < D_; ++j_)                                       \
            gstep8v(wxp0[j_], wxp1[j_], xv[2 * j_], xv[2 * j_ + 1], A1_, B1_);\
        const ulonglong2* h0v = (const ulonglong2*)&hs[w][0][rb_][0][0];      \
        _Pragma("unroll")                                                     \
        for (int jq_ = 0; jq_ < 4; ++jq_) {                                   \
            float4 w20 = *(const float4*)&wsm[0][r0][4 * jq_];                \
            float4 w21 = *(const float4*)&wsm[0][r1][4 * jq_];                \
            _Pragma("unroll")                                                 \
            for (int jj_ = 0; jj_ < 4; ++jj_) {                               \
                int j_ = 4 * jq_ + jj_;                                       \
                ulonglong2 v01 = h0v[2 * j_], v23 = h0v[2 * j_ + 1];          \
                gstep8v(whp0[j_], whp1[j_], v01, v23, A1_, B1_);              \
                float s0 = ((const float*)&w20)[jj_];                         \
                float s1 = ((const float*)&w21)[jj_];                         \
                gstep8v(pack2(s0, s0), pack2(s1, s1), v01, v23, A2_, B2_);    \
            }                                                                 \
        }                                                                     \
    }                                                                         \
    if (U1) do_update8(A1_, B1_, low, c1p0, c1p1,                             \
                       &hs[w][0][wb_][unit][0] + hoff);                       \
    /* block B */                                                             \
    _Pragma("unroll")                                                         \
    for (int k_ = 0; k_ < 4; ++k_) { A3_[k_] = bp3l; B3_[k_] = bp3h; }        \
    {                                                                         \
        const ulonglong2* h1v = (const ulonglong2*)&hs[w][1][rb_][0][0];      \
        _Pragma("unroll")                                                     \
        for (int jq_ = 0; jq_ < 4; ++jq_) {                                   \
            float4 w2h0 = *(const float4*)&wsm[0][r0][16 + 4 * jq_];          \
            float4 w2h1 = *(const float4*)&wsm[0][r1][16 + 4 * jq_];          \
            float4 w3i0 = *(const float4*)&wsm[1][r0][4 * jq_];               \
            float4 w3i1 = *(const float4*)&wsm[1][r1][4 * jq_];               \
            _Pragma("unroll")                                                 \
            for (int jj_ = 0; jj_ < 4; ++jj_) {                               \
                int j_ = 4 * jq_ + jj_;                                       \
                ulonglong2 v01 = h1v[2 * j_], v23 = h1v[2 * j_ + 1];          \
                float s0 = ((const float*)&w2h0)[jj_];                        \
                float s1 = ((const float*)&w2h1)[jj_];                        \
                gstep8v(pack2(s0, s0), pack2(s1, s1), v01, v23, A2_, B2_);    \
                float t0 = ((const float*)&w3i0)[jj_];                        \
                float t1 = ((const float*)&w3i1)[jj_];                        \
                gstep8v(pack2(t0, t0), pack2(t1, t1), v01, v23, A3_, B3_);    \
            }                                                                 \
        }                                                                     \
    }                                                                         \
    if (U2) do_update8(A2_, B2_, low, c2p0, c2p1,                             \
                       &hs[w][1][wb_][unit][0] + hoff);                       \
    /* block C */                                                             \
    {                                                                         \
        const ulonglong2* h2v = (const ulonglong2*)&hs[w][2][rb_][0][0];      \
        _Pragma("unroll")                                                     \
        for (int jq_ = 0; jq_ < 4; ++jq_) {                                   \
            float4 w3h0 = *(const float4*)&wsm[1][r0][16 + 4 * jq_];          \
            float4 w3h1 = *(const float4*)&wsm[1][r1][16 + 4 * jq_];          \
            _Pragma("unroll")                                                 \
            for (int jj_ = 0; jj_ < 4; ++jj_) {                               \
                int j_ = 4 * jq_ + jj_;                                       \
                float s0 = ((const float*)&w3h0)[jj_];                        \
                float s1 = ((const float*)&w3h1)[jj_];                        \
                gstep8v(pack2(s0, s0), pack2(s1, s1),                         \
                        h2v[2 * j_], h2v[2 * j_ + 1], A3_, B3_);              \
            }                                                                 \
        }                                                                     \
    }                                                                         \
    if (U3) h3f = do_update8(A3_, B3_, low, c3p0, c3p1,                       \
                             &hs[w][2][wb_][unit][0] + hoff);                 \
    xs[w][wb_][xj][xc] = xn_;                                                 \
    __syncwarp();                                                             \
} while (0)

    ITER(0, true, false, false);
    ITER(1, true, true, false);
#pragma unroll 1
    for (int k = 2; k < T_; ++k) ITER(k, true, true, true);
    ITER(T_, false, true, true);
    ITER(T_ + 1, false, false, true);
#undef ITER

    // final layer-3 h (step T-1): low lane -> chains 0-3; high -> 4-7.
    {
        int cb = b0 + (low ? 0 : 4);
        g_h3[dir][cb + 0][unit] = h3f.x;
        g_h3[dir][cb + 1][unit] = h3f.y;
        g_h3[dir][cb + 2][unit] = h3f.z;
        g_h3[dir][cb + 3][unit] = h3f.w;
    }
}

// out[b,k] = b_out[k] + sum_j W_out[k][j]*hf3[b][j] + W_out[k][16+j]*hb3[b][j]
__global__ void proj_kernel(const float* __restrict__ Wo,
                            const float* __restrict__ bo,
                            float* __restrict__ out) {
    int b = blockIdx.x * blockDim.x + threadIdx.x;
    if (b >= B_) return;
    float a0 = bo[0], a1 = bo[1], a2 = bo[2], a3 = bo[3];
#pragma unroll
    for (int j = 0; j < H_; ++j) {
        float hf = g_h3[0][b][j];
        a0 += Wo[0 * 32 + j] * hf;
        a1 += Wo[1 * 32 + j] * hf;
        a2 += Wo[2 * 32 + j] * hf;
        a3 += Wo[3 * 32 + j] * hf;
    }
#pragma unroll
    for (int j = 0; j < H_; ++j) {
        float hb = g_h3[1][b][j];
        a0 += Wo[0 * 32 + 16 + j] * hb;
        a1 += Wo[1 * 32 + 16 + j] * hb;
        a2 += Wo[2 * 32 + 16 + j] * hb;
        a3 += Wo[3 * 32 + 16 + j] * hb;
    }
    ((float4*)out)[b] = make_float4(a0, a1, a2, a3);
}

extern "C" void kernel_launch(void* const* d_in, const int* in_sizes, int n_in,
                              void* d_out, int out_size) {
    (void)in_sizes; (void)n_in; (void)out_size;
    Params p;
    p.y = (const float*)d_in[0];
    for (int i = 0; i < 24; ++i) p.w[i] = (const float*)d_in[1 + i];

    lstm_kernel<<<NCTA, 256>>>(p);
    proj_kernel<<<(B_ + 127) / 128, 128>>>((const float*)d_in[25],
                                           (const float*)d_in[26],
                                           (float*)d_out);
}